// round 1
// baseline (speedup 1.0000x reference)
#include <cuda_runtime.h>

#define BB 8
#define TT 4096
#define EE 1024
#define HH 128
#define MM (BB*TT)

// Scratch for q, k, v projections (16.8 MB each). __device__ globals: no allocs.
static __device__ float g_q[(size_t)MM * HH];
static __device__ float g_k[(size_t)MM * HH];
static __device__ float g_v[(size_t)MM * HH];

// ---------------------------------------------------------------------------
// Kernel 1: QKV projection GEMM.  out[64x128] tile = x[64x1024] @ W[1024x128] + b
// grid: (MM/64, 3)  — blockIdx.y selects q/k/v.  block: 256 threads (16x16),
// each thread computes a 4x8 microtile.
// ---------------------------------------------------------------------------
__global__ __launch_bounds__(256) void qkv_kernel(
    const float* __restrict__ x,
    const float* __restrict__ Wq, const float* __restrict__ bq,
    const float* __restrict__ Wk, const float* __restrict__ bk,
    const float* __restrict__ Wv, const float* __restrict__ bv)
{
    __shared__ float xs[64][17];     // +1 pad
    __shared__ float ws[16][128];

    const float* W; const float* bias; float* out;
    if (blockIdx.y == 0)      { W = Wq; bias = bq; out = g_q; }
    else if (blockIdx.y == 1) { W = Wk; bias = bk; out = g_k; }
    else                      { W = Wv; bias = bv; out = g_v; }

    const int t  = threadIdx.x;
    const int tr = t >> 4, tc = t & 15;
    const int i0 = tr * 4, c0 = tc * 8;
    const int m0 = blockIdx.x * 64;

    float acc[4][8];
#pragma unroll
    for (int r = 0; r < 4; r++)
#pragma unroll
        for (int c = 0; c < 8; c++) acc[r][c] = 0.f;

    const int xrow = t >> 2;
    const int xcol = (t & 3) * 4;

    for (int k0 = 0; k0 < EE; k0 += 16) {
        // x tile 64x16 (one float4 per thread)
        float4 xv = *(const float4*)(x + (size_t)(m0 + xrow) * EE + k0 + xcol);
        xs[xrow][xcol + 0] = xv.x;
        xs[xrow][xcol + 1] = xv.y;
        xs[xrow][xcol + 2] = xv.z;
        xs[xrow][xcol + 3] = xv.w;
        // W tile 16x128 (two float4 per thread)
#pragma unroll
        for (int u = 0; u < 2; u++) {
            int f  = u * 256 + t;
            int kk = f >> 5;
            int c  = (f & 31) * 4;
            *(float4*)&ws[kk][c] = *(const float4*)(W + (size_t)(k0 + kk) * HH + c);
        }
        __syncthreads();

#pragma unroll
        for (int kk = 0; kk < 16; kk++) {
            float xr[4];
#pragma unroll
            for (int r = 0; r < 4; r++) xr[r] = xs[i0 + r][kk];
            float4 w0 = *(float4*)&ws[kk][c0];
            float4 w1 = *(float4*)&ws[kk][c0 + 4];
#pragma unroll
            for (int r = 0; r < 4; r++) {
                acc[r][0] = fmaf(xr[r], w0.x, acc[r][0]);
                acc[r][1] = fmaf(xr[r], w0.y, acc[r][1]);
                acc[r][2] = fmaf(xr[r], w0.z, acc[r][2]);
                acc[r][3] = fmaf(xr[r], w0.w, acc[r][3]);
                acc[r][4] = fmaf(xr[r], w1.x, acc[r][4]);
                acc[r][5] = fmaf(xr[r], w1.y, acc[r][5]);
                acc[r][6] = fmaf(xr[r], w1.z, acc[r][6]);
                acc[r][7] = fmaf(xr[r], w1.w, acc[r][7]);
            }
        }
        __syncthreads();
    }

#pragma unroll
    for (int r = 0; r < 4; r++) {
        float* dst = out + (size_t)(m0 + i0 + r) * HH + c0;
        float4 b0 = make_float4(acc[r][0] + bias[c0 + 0], acc[r][1] + bias[c0 + 1],
                                acc[r][2] + bias[c0 + 2], acc[r][3] + bias[c0 + 3]);
        float4 b1 = make_float4(acc[r][4] + bias[c0 + 4], acc[r][5] + bias[c0 + 5],
                                acc[r][6] + bias[c0 + 6], acc[r][7] + bias[c0 + 7]);
        *(float4*)(dst)     = b0;
        *(float4*)(dst + 4) = b1;
    }
}

// ---------------------------------------------------------------------------
// Kernel 2: causal flash attention, fp32, online softmax.
// grid: (TT/64, BB). block: 256 threads (16x16).
//   S microtile 4x4 per thread; O microtile 4x8 per thread.
// Dynamic smem: q[64][129] + k[64][129] + v[64][128] + p[64][65] = 115456 B.
// ---------------------------------------------------------------------------
#define QK_STRIDE 129
#define V_STRIDE  128
#define P_STRIDE  65
#define SM_FLOATS (64*QK_STRIDE*2 + 64*V_STRIDE + 64*P_STRIDE)
#define SM_BYTES  (SM_FLOATS * 4)

__global__ __launch_bounds__(256, 2) void attn_kernel(float* __restrict__ out)
{
    extern __shared__ float sm[];
    float* qs = sm;
    float* ks = sm + 64 * QK_STRIDE;
    float* vs = ks + 64 * QK_STRIDE;
    float* ps = vs + 64 * V_STRIDE;

    const int t  = threadIdx.x;
    const int tr = t >> 4, tc = t & 15;
    const int i0 = tr * 4, j0 = tc * 4, c0 = tc * 8;
    const int qt = blockIdx.x, b = blockIdx.y;

    const float SCALE = 0.08838834764831845f;   // 1/sqrt(128)

    // load + pre-scale q tile
    const float* gq = g_q + ((size_t)b * TT + (size_t)qt * 64) * HH;
#pragma unroll
    for (int u = 0; u < 8; u++) {
        int f   = u * 256 + t;
        int row = f >> 5;
        int col = (f & 31) << 2;
        float4 v4 = *(const float4*)(gq + row * HH + col);
        float* d  = qs + row * QK_STRIDE + col;
        d[0] = v4.x * SCALE; d[1] = v4.y * SCALE;
        d[2] = v4.z * SCALE; d[3] = v4.w * SCALE;
    }

    float o[4][8];
    float m[4], l[4];
#pragma unroll
    for (int r = 0; r < 4; r++) {
        m[r] = -3.0e38f; l[r] = 0.f;
#pragma unroll
        for (int c = 0; c < 8; c++) o[r][c] = 0.f;
    }

    for (int st = 0; st <= qt; st++) {
        const float* gk = g_k + ((size_t)b * TT + (size_t)st * 64) * HH;
        const float* gv = g_v + ((size_t)b * TT + (size_t)st * 64) * HH;
#pragma unroll
        for (int u = 0; u < 8; u++) {
            int f   = u * 256 + t;
            int row = f >> 5;
            int col = (f & 31) << 2;
            float4 k4 = *(const float4*)(gk + row * HH + col);
            float* d  = ks + row * QK_STRIDE + col;
            d[0] = k4.x; d[1] = k4.y; d[2] = k4.z; d[3] = k4.w;
            *(float4*)(vs + row * V_STRIDE + col) =
                *(const float4*)(gv + row * HH + col);
        }
        __syncthreads();

        // S = q @ k^T  (4x4 per thread)
        float s[4][4];
#pragma unroll
        for (int r = 0; r < 4; r++)
#pragma unroll
            for (int c = 0; c < 4; c++) s[r][c] = 0.f;

        const float* qp = qs + i0 * QK_STRIDE;
        const float* kp = ks + j0 * QK_STRIDE;
#pragma unroll 4
        for (int h = 0; h < HH; h++) {
            float qr[4], kc[4];
#pragma unroll
            for (int r = 0; r < 4; r++) qr[r] = qp[r * QK_STRIDE + h];
#pragma unroll
            for (int c = 0; c < 4; c++) kc[c] = kp[c * QK_STRIDE + h];
#pragma unroll
            for (int r = 0; r < 4; r++)
#pragma unroll
                for (int c = 0; c < 4; c++)
                    s[r][c] = fmaf(qr[r], kc[c], s[r][c]);
        }

        if (st == qt) {   // diagonal tile: causal mask
#pragma unroll
            for (int r = 0; r < 4; r++)
#pragma unroll
                for (int c = 0; c < 4; c++)
                    if (j0 + c > i0 + r) s[r][c] = -1.0e30f;
        }

        // online softmax (row stats shared across the 16 col-owner lanes)
#pragma unroll
        for (int r = 0; r < 4; r++) {
            float lm = fmaxf(fmaxf(s[r][0], s[r][1]), fmaxf(s[r][2], s[r][3]));
#pragma unroll
            for (int off = 8; off; off >>= 1)
                lm = fmaxf(lm, __shfl_xor_sync(0xffffffffu, lm, off, 16));
            float mn    = fmaxf(m[r], lm);
            float alpha = __expf(m[r] - mn);
            m[r] = mn;
            float ls = 0.f;
#pragma unroll
            for (int c = 0; c < 4; c++) {
                float p = __expf(s[r][c] - mn);
                s[r][c] = p;
                ls += p;
            }
#pragma unroll
            for (int off = 8; off; off >>= 1)
                ls += __shfl_xor_sync(0xffffffffu, ls, off, 16);
            l[r] = l[r] * alpha + ls;
#pragma unroll
            for (int c = 0; c < 8; c++) o[r][c] *= alpha;
            float* pd = ps + (i0 + r) * P_STRIDE + j0;
            pd[0] = s[r][0]; pd[1] = s[r][1]; pd[2] = s[r][2]; pd[3] = s[r][3];
        }
        __syncthreads();

        // O += P @ V   (4x8 per thread)
#pragma unroll 2
        for (int j = 0; j < 64; j++) {
            float4 va = *(float4*)(vs + j * V_STRIDE + c0);
            float4 vb = *(float4*)(vs + j * V_STRIDE + c0 + 4);
#pragma unroll
            for (int r = 0; r < 4; r++) {
                float p = ps[(i0 + r) * P_STRIDE + j];
                o[r][0] = fmaf(p, va.x, o[r][0]);
                o[r][1] = fmaf(p, va.y, o[r][1]);
                o[r][2] = fmaf(p, va.z, o[r][2]);
                o[r][3] = fmaf(p, va.w, o[r][3]);
                o[r][4] = fmaf(p, vb.x, o[r][4]);
                o[r][5] = fmaf(p, vb.y, o[r][5]);
                o[r][6] = fmaf(p, vb.z, o[r][6]);
                o[r][7] = fmaf(p, vb.w, o[r][7]);
            }
        }
        __syncthreads();
    }

    float* dst = out + ((size_t)b * TT + (size_t)qt * 64) * HH;
#pragma unroll
    for (int r = 0; r < 4; r++) {
        float inv = 1.0f / l[r];
        float4 w0 = make_float4(o[r][0] * inv, o[r][1] * inv,
                                o[r][2] * inv, o[r][3] * inv);
        float4 w1 = make_float4(o[r][4] * inv, o[r][5] * inv,
                                o[r][6] * inv, o[r][7] * inv);
        float* p = dst + (i0 + r) * HH + c0;
        *(float4*)(p)     = w0;
        *(float4*)(p + 4) = w1;
    }
}

// ---------------------------------------------------------------------------
extern "C" void kernel_launch(void* const* d_in, const int* in_sizes, int n_in,
                              void* d_out, int out_size)
{
    const float* x  = (const float*)d_in[0];
    const float* Wq = (const float*)d_in[1];
    const float* bq = (const float*)d_in[2];
    const float* Wk = (const float*)d_in[3];
    const float* bk = (const float*)d_in[4];
    const float* Wv = (const float*)d_in[5];
    const float* bv = (const float*)d_in[6];
    float* out = (float*)d_out;

    // idempotent, host-side, non-stream op: safe under graph capture
    cudaFuncSetAttribute(attn_kernel,
                         cudaFuncAttributeMaxDynamicSharedMemorySize, SM_BYTES);

    qkv_kernel<<<dim3(MM / 64, 3), 256>>>(x, Wq, bq, Wk, bk, Wv, bv);
    attn_kernel<<<dim3(TT / 64, BB), 256, SM_BYTES>>>(out);
}

// round 2
// speedup vs baseline: 2.6471x; 2.6471x over previous
#include <cuda_runtime.h>
#include <cstdint>

#define BB 8
#define TT 4096
#define EE 1024
#define HH 128
#define MM (BB*TT)

// ---------------------------------------------------------------------------
// Scratch: q/k/v in tf32, PRE-PACKED into mma.sync fragment order.
// g_q: per 128-row tile: qf[rb 0..7][s 0..15][lane 32][word 4]   (A-frags)
// g_k: per 64-row kv tile: kf[j 0..7][s 0..15][lane 32][word 2]  (B-frags, S=QK^T)
// g_v: per 64-row kv tile: vf[ht 0..15][skv 0..7][lane 32][word 2](B-frags, O=PV)
// ---------------------------------------------------------------------------
static __device__ __align__(16) float g_q[(size_t)MM * HH];
static __device__ __align__(16) float g_k[(size_t)MM * HH];
static __device__ __align__(16) float g_v[(size_t)MM * HH];

__device__ __forceinline__ unsigned f2tf(float f) {
    unsigned u;
    asm("cvt.rna.tf32.f32 %0, %1;" : "=r"(u) : "f"(f));
    return u;
}

__device__ __forceinline__ void mma_tf32(float4& d, const uint4& a, const uint2& b) {
    asm volatile(
        "mma.sync.aligned.m16n8k8.row.col.f32.tf32.tf32.f32 "
        "{%0,%1,%2,%3}, {%4,%5,%6,%7}, {%8,%9}, {%0,%1,%2,%3};"
        : "+f"(d.x), "+f"(d.y), "+f"(d.z), "+f"(d.w)
        : "r"(a.x), "r"(a.y), "r"(a.z), "r"(a.w), "r"(b.x), "r"(b.y));
}

__device__ __forceinline__ void cpasync16(void* sdst, const void* gsrc) {
    unsigned s = (unsigned)__cvta_generic_to_shared(sdst);
    asm volatile("cp.async.cg.shared.global [%0], [%1], 16;" :: "r"(s), "l"(gsrc));
}
#define CP_COMMIT() asm volatile("cp.async.commit_group;")
template <int N> __device__ __forceinline__ void cp_wait() {
    asm volatile("cp.async.wait_group %0;" :: "n"(N));
}

// ---------------------------------------------------------------------------
// Kernel 1: QKV GEMM (tf32 mma). CTA: 128 rows x 128 cols, K=1024.
// 8 warps: rg = w&3 (rows rg*32, rowblocks 2rg,2rg+1), cg = w>>2 (cols cg*64).
// Epilogue writes fragment-packed tf32 to g_q / g_k / g_v.
// dynamic smem: chunk bufs 16384 f  |  epilogue plain buf 128x132 = 16896 f
// ---------------------------------------------------------------------------
#define SP 132
#define QKV_SMEM (128 * SP * 4)   // 67584 B (>= 16384*4)

__global__ __launch_bounds__(256) void qkv_mma_kernel(
    const float* __restrict__ x,
    const float* __restrict__ Wq, const float* __restrict__ bq,
    const float* __restrict__ Wk, const float* __restrict__ bk,
    const float* __restrict__ Wv, const float* __restrict__ bv)
{
    extern __shared__ float smq[];
    unsigned* xfu = (unsigned*)smq;            // 8192 words
    unsigned* wfu = (unsigned*)(smq + 8192);   // 8192 words
    float*    sp  = smq;                       // epilogue reuse

    const int by = blockIdx.y;
    const float* W; const float* bias; float* outg;
    if (by == 0)      { W = Wq; bias = bq; outg = g_q; }
    else if (by == 1) { W = Wk; bias = bk; outg = g_k; }
    else              { W = Wv; bias = bv; outg = g_v; }

    const int t    = threadIdx.x;
    const int w    = t >> 5;
    const int lane = t & 31;
    const int g    = lane >> 2;
    const int tig  = lane & 3;
    const int rg   = w & 3;
    const int cg   = w >> 2;
    const int m0   = blockIdx.x * 128;

    float4 acc[2][8];
#pragma unroll
    for (int i = 0; i < 2; i++)
#pragma unroll
        for (int j = 0; j < 8; j++) acc[i][j] = make_float4(0.f, 0.f, 0.f, 0.f);

    for (int kc = 0; kc < EE; kc += 64) {
        // load x chunk 128x64 -> xf frags
#pragma unroll
        for (int u = 0; u < 8; u++) {
            int idx4 = u * 256 + t;
            int row = idx4 >> 4;
            int c   = (idx4 & 15) * 4;
            float4 xv = *(const float4*)(x + (size_t)(m0 + row) * EE + kc + c);
            float vv[4] = {xv.x, xv.y, xv.z, xv.w};
            int rb = row >> 4, r_in = row & 15;
            int gg = r_in & 7, w0 = (r_in >> 3) & 1;
#pragma unroll
            for (int i = 0; i < 4; i++) {
                int ci = c + i;
                int s = ci >> 3, cin = ci & 7;
                int tg = cin & 3, w2 = (cin >= 4) ? 2 : 0;
                xfu[((rb * 8 + s) * 32 + gg * 4 + tg) * 4 + w0 + w2] = f2tf(vv[i]);
            }
        }
        // load W chunk 64x128 -> wf frags
#pragma unroll
        for (int u = 0; u < 8; u++) {
            int idx4 = u * 256 + t;
            int k  = idx4 >> 5;
            int n  = (idx4 & 31) * 4;
            float4 wv = *(const float4*)(W + (size_t)(kc + k) * HH + n);
            float vv[4] = {wv.x, wv.y, wv.z, wv.w};
            int s = k >> 3, kin = k & 7;
            int tg = kin & 3, wb = (kin >= 4) ? 1 : 0;
#pragma unroll
            for (int i = 0; i < 4; i++) {
                int ni = n + i;
                int j = ni >> 3, gg = ni & 7;
                wfu[((j * 8 + s) * 32 + gg * 4 + tg) * 2 + wb] = f2tf(vv[i]);
            }
        }
        __syncthreads();

#pragma unroll
        for (int s = 0; s < 8; s++) {
            uint4 a0 = *(const uint4*)(xfu + (((2 * rg) * 8 + s) * 32 + lane) * 4);
            uint4 a1 = *(const uint4*)(xfu + (((2 * rg + 1) * 8 + s) * 32 + lane) * 4);
#pragma unroll
            for (int j = 0; j < 8; j++) {
                uint2 b = *(const uint2*)(wfu + (((cg * 8 + j) * 8 + s) * 32 + lane) * 2);
                mma_tf32(acc[0][j], a0, b);
                mma_tf32(acc[1][j], a1, b);
            }
        }
        __syncthreads();
    }

    // bias (+ scale for q), store to plain smem
    const float SCALE = 0.08838834764831845f;   // 1/sqrt(128)
    const float sc = (by == 0) ? SCALE : 1.0f;
#pragma unroll
    for (int i = 0; i < 2; i++) {
        int r0 = rg * 32 + i * 16 + g;
#pragma unroll
        for (int j = 0; j < 8; j++) {
            int c0 = cg * 64 + j * 8 + 2 * tig;
            float b0 = __ldg(bias + c0), b1 = __ldg(bias + c0 + 1);
            float4 a = acc[i][j];
            *(float2*)&sp[r0 * SP + c0]       = make_float2((a.x + b0) * sc, (a.y + b1) * sc);
            *(float2*)&sp[(r0 + 8) * SP + c0] = make_float2((a.z + b0) * sc, (a.w + b1) * sc);
        }
    }
    __syncthreads();

    const int bx = blockIdx.x;
    if (by == 0) {
        // A-frag pack: 128 (rb,s) pairs, 16 per warp (rb = w, s = i)
        unsigned* dst = (unsigned*)(outg + (size_t)bx * 16384);
#pragma unroll
        for (int i = 0; i < 16; i++) {
            float v0 = sp[(w * 16 + g)     * SP + 8 * i + tig];
            float v1 = sp[(w * 16 + g + 8) * SP + 8 * i + tig];
            float v2 = sp[(w * 16 + g)     * SP + 8 * i + tig + 4];
            float v3 = sp[(w * 16 + g + 8) * SP + 8 * i + tig + 4];
            uint4 o = make_uint4(f2tf(v0), f2tf(v1), f2tf(v2), f2tf(v3));
            *(uint4*)(dst + ((w * 16 + i) * 32 + lane) * 4) = o;
        }
    } else if (by == 1) {
        // K B-frags per 64-row kv tile
#pragma unroll
        for (int it = 0; it < 32; it++) {
            int idx = w * 32 + it;
            int kt = idx >> 7, j = (idx >> 4) & 7, s = idx & 15;
            int row = kt * 64 + 8 * j + g;
            float v0 = sp[row * SP + 8 * s + tig];
            float v1 = sp[row * SP + 8 * s + tig + 4];
            unsigned* dst = (unsigned*)(outg + (size_t)(2 * bx + kt) * 8192);
            *(uint2*)(dst + ((j * 16 + s) * 32 + lane) * 2) = make_uint2(f2tf(v0), f2tf(v1));
        }
    } else {
        // V B-frags per 64-row kv tile
#pragma unroll
        for (int it = 0; it < 32; it++) {
            int idx = w * 32 + it;
            int kt = idx >> 7, ht = (idx >> 3) & 15, skv = idx & 7;
            float v0 = sp[(kt * 64 + 8 * skv + tig)     * SP + 8 * ht + g];
            float v1 = sp[(kt * 64 + 8 * skv + tig + 4) * SP + 8 * ht + g];
            unsigned* dst = (unsigned*)(outg + (size_t)(2 * bx + kt) * 8192);
            *(uint2*)(dst + ((ht * 8 + skv) * 32 + lane) * 2) = make_uint2(f2tf(v0), f2tf(v1));
        }
    }
}

// ---------------------------------------------------------------------------
// Kernel 2: flash attention, tf32 mma. CTA: 128 q-rows; kv tiles of 64,
// double-buffered via cp.async. 8 warps x 16 q-rows (no col split).
// smem floats: qs 16384 | ks[2] 8192 ea | vs[2] 8192 ea | pf 8192 = 57344 f.
// ---------------------------------------------------------------------------
#define ATT_SMEM (57344 * 4)      // 229376 B

__global__ __launch_bounds__(256, 1) void attn_mma_kernel(float* __restrict__ out)
{
    extern __shared__ float sm[];
    unsigned* qsu = (unsigned*)sm;                 // 16384 w
    const int KS0 = 16384, VS0 = 32768, PF0 = 49152;

    const int t    = threadIdx.x;
    const int w    = t >> 5;
    const int lane = t & 31;
    const int g    = lane >> 2;
    const int tig  = lane & 3;

    const int qt = 31 - blockIdx.x;     // heavy tiles first
    const int b  = blockIdx.y;

    // load Q tile (already packed+tf32)
    {
        const float4* src = (const float4*)(g_q + (size_t)(b * 32 + qt) * 16384);
        float4* dst = (float4*)sm;
#pragma unroll
        for (int u = 0; u < 16; u++) dst[u * 256 + t] = src[u * 256 + t];
    }

    const int ntiles = 2 * qt + 2;
    // prefetch tile 0
    {
        const float* kg = g_k + (size_t)(b * 64) * 8192;
        const float* vg = g_v + (size_t)(b * 64) * 8192;
#pragma unroll
        for (int u = 0; u < 8; u++) {
            int idx = u * 256 + t;
            cpasync16(sm + KS0 + idx * 4, kg + idx * 4);
            cpasync16(sm + VS0 + idx * 4, vg + idx * 4);
        }
        CP_COMMIT();
    }

    float4 O[16];
#pragma unroll
    for (int ht = 0; ht < 16; ht++) O[ht] = make_float4(0.f, 0.f, 0.f, 0.f);
    float mrow[2] = {-3.0e38f, -3.0e38f};
    float lrow[2] = {0.f, 0.f};

    for (int st = 0; st < ntiles; st++) {
        const int buf = st & 1;
        if (st + 1 < ntiles) {
            const float* kg = g_k + (size_t)(b * 64 + st + 1) * 8192;
            const float* vg = g_v + (size_t)(b * 64 + st + 1) * 8192;
            float* kd = sm + KS0 + (buf ^ 1) * 8192;
            float* vd = sm + VS0 + (buf ^ 1) * 8192;
#pragma unroll
            for (int u = 0; u < 8; u++) {
                int idx = u * 256 + t;
                cpasync16(kd + idx * 4, kg + idx * 4);
                cpasync16(vd + idx * 4, vg + idx * 4);
            }
            CP_COMMIT();
            cp_wait<1>();
        } else {
            cp_wait<0>();
        }
        __syncthreads();

        const unsigned* ksu = (const unsigned*)(sm + KS0 + buf * 8192);
        const unsigned* vsu = (const unsigned*)(sm + VS0 + buf * 8192);

        // ---- S = Q @ K^T  (per warp: 16 x 64) ----
        float4 sa[8];
#pragma unroll
        for (int j = 0; j < 8; j++) sa[j] = make_float4(0.f, 0.f, 0.f, 0.f);
#pragma unroll
        for (int s = 0; s < 16; s++) {
            uint4 a = *(const uint4*)(qsu + ((w * 16 + s) * 32 + lane) * 4);
#pragma unroll
            for (int j = 0; j < 8; j++) {
                uint2 bb = *(const uint2*)(ksu + ((j * 16 + s) * 32 + lane) * 2);
                mma_tf32(sa[j], a, bb);
            }
        }

        // ---- causal mask (only the last two tiles can cross the diagonal) ----
        if (st >= 2 * qt) {
            const int rbase = qt * 128 + w * 16 + g;
#pragma unroll
            for (int j = 0; j < 8; j++) {
                int kv0 = st * 64 + 8 * j + 2 * tig;
                if (kv0     > rbase)     sa[j].x = -1.0e30f;
                if (kv0 + 1 > rbase)     sa[j].y = -1.0e30f;
                if (kv0     > rbase + 8) sa[j].z = -1.0e30f;
                if (kv0 + 1 > rbase + 8) sa[j].w = -1.0e30f;
            }
        }

        // ---- online softmax (rows g and g+8; reduce over 4 tig lanes) ----
#pragma unroll
        for (int h = 0; h < 2; h++) {
            float lm = -3.0e38f;
#pragma unroll
            for (int j = 0; j < 8; j++) {
                float v0 = h ? sa[j].z : sa[j].x;
                float v1 = h ? sa[j].w : sa[j].y;
                lm = fmaxf(lm, fmaxf(v0, v1));
            }
            lm = fmaxf(lm, __shfl_xor_sync(0xffffffffu, lm, 1));
            lm = fmaxf(lm, __shfl_xor_sync(0xffffffffu, lm, 2));
            float mn    = fmaxf(mrow[h], lm);
            float alpha = __expf(mrow[h] - mn);
            mrow[h] = mn;
            float ls = 0.f;
#pragma unroll
            for (int j = 0; j < 8; j++) {
                float v0 = h ? sa[j].z : sa[j].x;
                float v1 = h ? sa[j].w : sa[j].y;
                v0 = __expf(v0 - mn);
                v1 = __expf(v1 - mn);
                if (h) { sa[j].z = v0; sa[j].w = v1; }
                else   { sa[j].x = v0; sa[j].y = v1; }
                ls += v0 + v1;
            }
            ls += __shfl_xor_sync(0xffffffffu, ls, 1);
            ls += __shfl_xor_sync(0xffffffffu, ls, 2);
            lrow[h] = lrow[h] * alpha + ls;
#pragma unroll
            for (int ht = 0; ht < 16; ht++) {
                if (h) { O[ht].z *= alpha; O[ht].w *= alpha; }
                else   { O[ht].x *= alpha; O[ht].y *= alpha; }
            }
        }

        // ---- P -> A-frags via warp-private smem bounce ----
        {
            unsigned* pfu = (unsigned*)(sm + PF0);
            const int col0  = (2 * tig) & 3;
            const int tigHi = (tig >= 2) ? 2 : 0;
#pragma unroll
            for (int j = 0; j < 8; j++) {
                int base = ((w * 8 + j) * 32 + g * 4 + col0) * 4 + tigHi;
                pfu[base]     = f2tf(sa[j].x);
                pfu[base + 4] = f2tf(sa[j].y);
                pfu[base + 1] = f2tf(sa[j].z);
                pfu[base + 5] = f2tf(sa[j].w);
            }
            __syncwarp();

            // ---- O += P @ V ----
#pragma unroll
            for (int skv = 0; skv < 8; skv++) {
                uint4 a = *(const uint4*)(pfu + ((w * 8 + skv) * 32 + lane) * 4);
#pragma unroll
                for (int ht = 0; ht < 16; ht++) {
                    uint2 bb = *(const uint2*)(vsu + ((ht * 8 + skv) * 32 + lane) * 2);
                    mma_tf32(O[ht], a, bb);
                }
            }
        }
        __syncthreads();
    }

    // ---- epilogue ----
    const float inv0 = 1.0f / lrow[0];
    const float inv1 = 1.0f / lrow[1];
    const int r0 = qt * 128 + w * 16 + g;
    float* o0 = out + ((size_t)b * TT + r0) * HH;
    float* o1 = o0 + 8 * HH;
#pragma unroll
    for (int ht = 0; ht < 16; ht++) {
        int col = ht * 8 + 2 * tig;
        *(float2*)(o0 + col) = make_float2(O[ht].x * inv0, O[ht].y * inv0);
        *(float2*)(o1 + col) = make_float2(O[ht].z * inv1, O[ht].w * inv1);
    }
}

// ---------------------------------------------------------------------------
extern "C" void kernel_launch(void* const* d_in, const int* in_sizes, int n_in,
                              void* d_out, int out_size)
{
    const float* x  = (const float*)d_in[0];
    const float* Wq = (const float*)d_in[1];
    const float* bq = (const float*)d_in[2];
    const float* Wk = (const float*)d_in[3];
    const float* bk = (const float*)d_in[4];
    const float* Wv = (const float*)d_in[5];
    const float* bv = (const float*)d_in[6];
    float* out = (float*)d_out;

    cudaFuncSetAttribute(qkv_mma_kernel,
                         cudaFuncAttributeMaxDynamicSharedMemorySize, QKV_SMEM);
    cudaFuncSetAttribute(attn_mma_kernel,
                         cudaFuncAttributeMaxDynamicSharedMemorySize, ATT_SMEM);

    qkv_mma_kernel<<<dim3(MM / 128, 3), 256, QKV_SMEM>>>(x, Wq, bq, Wk, bk, Wv, bv);
    attn_mma_kernel<<<dim3(TT / 128, BB), 256, ATT_SMEM>>>(out);
}

// round 3
// speedup vs baseline: 5.7836x; 2.1849x over previous
#include <cuda_runtime.h>
#include <cstdint>

#define BB 8
#define TT 4096
#define EE 1024
#define HH 128
#define MM (BB*TT)

// ---------------------------------------------------------------------------
// Scratch: q/k/v in tf32, PRE-PACKED into mma.sync fragment order (validated R2).
// g_q: per 128-row tile: [rb*16+s][lane][4 words]  (A-frags)
// g_k: per 64-row kv tile: [j*16+s][lane][2 words] (B-frags for S=QK^T)
// g_v: per 64-row kv tile: [ht*8+skv][lane][2 words](B-frags for O=PV)
// ---------------------------------------------------------------------------
static __device__ __align__(16) float g_q[(size_t)MM * HH];
static __device__ __align__(16) float g_k[(size_t)MM * HH];
static __device__ __align__(16) float g_v[(size_t)MM * HH];

__device__ __forceinline__ unsigned f2tf(float f) {
    unsigned u;
    asm("cvt.rna.tf32.f32 %0, %1;" : "=r"(u) : "f"(f));
    return u;
}

__device__ __forceinline__ void mma_tf32(float4& d, const uint4& a, const uint2& b) {
    asm volatile(
        "mma.sync.aligned.m16n8k8.row.col.f32.tf32.tf32.f32 "
        "{%0,%1,%2,%3}, {%4,%5,%6,%7}, {%8,%9}, {%0,%1,%2,%3};"
        : "+f"(d.x), "+f"(d.y), "+f"(d.z), "+f"(d.w)
        : "r"(a.x), "r"(a.y), "r"(a.z), "r"(a.w), "r"(b.x), "r"(b.y));
}

__device__ __forceinline__ void cpasync16(void* sdst, const void* gsrc) {
    unsigned s = (unsigned)__cvta_generic_to_shared(sdst);
    asm volatile("cp.async.cg.shared.global [%0], [%1], 16;" :: "r"(s), "l"(gsrc));
}
#define CP_COMMIT() asm volatile("cp.async.commit_group;")
template <int N> __device__ __forceinline__ void cp_wait() {
    asm volatile("cp.async.wait_group %0;" :: "n"(N));
}

// ---------------------------------------------------------------------------
// Kernel 1: QKV GEMM. CTA 128x128, K-chunks of 32 double-buffered via cp.async
// into PLAIN padded smem (no pack stores). Fragment gather = conflict-free
// LDS.32 + cvt.rna in registers. Epilogue packs to g_q/g_k/g_v (runs once).
// smem: xs[2] 128x36f, ws[2] 32x136f  = 17920 floats = 71680 B.
// ---------------------------------------------------------------------------
#define XST 36
#define WST 136
#define XBUF (128*XST)     // 4608
#define WBUF (32*WST)      // 4352
#define QKV_SMEM (17920*4)
#define SP 132             // epilogue plain buffer stride (128*132=16896 <= 17920)

__global__ __launch_bounds__(256, 2) void qkv_mma_kernel(
    const float* __restrict__ x,
    const float* __restrict__ Wq, const float* __restrict__ bq,
    const float* __restrict__ Wk, const float* __restrict__ bk,
    const float* __restrict__ Wv, const float* __restrict__ bv)
{
    extern __shared__ float smq[];
    float* xsb[2] = { smq,           smq + XBUF };
    float* wsb[2] = { smq + 2*XBUF,  smq + 2*XBUF + WBUF };
    float* sp = smq;   // epilogue reuse

    const int by = blockIdx.y;
    const float* W; const float* bias; float* outg;
    if (by == 0)      { W = Wq; bias = bq; outg = g_q; }
    else if (by == 1) { W = Wk; bias = bk; outg = g_k; }
    else              { W = Wv; bias = bv; outg = g_v; }

    const int t    = threadIdx.x;
    const int w    = t >> 5;
    const int lane = t & 31;
    const int g    = lane >> 2;
    const int tig  = lane & 3;
    const int rg   = w & 3;
    const int cg   = w >> 2;
    const int m0   = blockIdx.x * 128;

    float4 acc[2][8];
#pragma unroll
    for (int i = 0; i < 2; i++)
#pragma unroll
        for (int j = 0; j < 8; j++) acc[i][j] = make_float4(0.f, 0.f, 0.f, 0.f);

    // chunk loader: x 128x32 (1024 f4), W 32x128 (1024 f4); 4 f4 each per thread
#define LOAD_CHUNK(KC, BUF) do {                                              \
        float* xd = xsb[BUF]; float* wd = wsb[BUF];                           \
        _Pragma("unroll")                                                     \
        for (int u = 0; u < 4; u++) {                                         \
            int idx = u * 256 + t;                                            \
            int row = idx >> 3, c4 = (idx & 7) * 4;                           \
            cpasync16(xd + row * XST + c4,                                    \
                      x + (size_t)(m0 + row) * EE + (KC) + c4);               \
        }                                                                     \
        _Pragma("unroll")                                                     \
        for (int u = 0; u < 4; u++) {                                         \
            int idx = u * 256 + t;                                            \
            int k = idx >> 5, c4 = (idx & 31) * 4;                            \
            cpasync16(wd + k * WST + c4,                                      \
                      W + (size_t)((KC) + k) * HH + c4);                      \
        }                                                                     \
        CP_COMMIT();                                                          \
    } while (0)

    LOAD_CHUNK(0, 0);

    for (int c = 0; c < 32; c++) {
        const int buf = c & 1;
        if (c < 31) { LOAD_CHUNK((c + 1) * 32, buf ^ 1); cp_wait<1>(); }
        else        { cp_wait<0>(); }
        __syncthreads();

        const float* xb = xsb[buf];
        const float* wb = wsb[buf];
#pragma unroll
        for (int s = 0; s < 4; s++) {
            uint4 a[2];
#pragma unroll
            for (int i = 0; i < 2; i++) {
                const float* xr0 = xb + ((2*rg + i)*16 + g)     * XST + s*8 + tig;
                const float* xr1 = xb + ((2*rg + i)*16 + g + 8) * XST + s*8 + tig;
                a[i].x = f2tf(xr0[0]); a[i].y = f2tf(xr1[0]);
                a[i].z = f2tf(xr0[4]); a[i].w = f2tf(xr1[4]);
            }
            const float* wr0 = wb + (s*8 + tig)     * WST + cg*64 + g;
            const float* wr1 = wb + (s*8 + tig + 4) * WST + cg*64 + g;
#pragma unroll
            for (int j = 0; j < 8; j++) {
                uint2 bf = make_uint2(f2tf(wr0[j*8]), f2tf(wr1[j*8]));
                mma_tf32(acc[0][j], a[0], bf);
                mma_tf32(acc[1][j], a[1], bf);
            }
        }
        __syncthreads();
    }

    // ---- epilogue (validated in R2): bias (+q scale) -> plain smem -> pack ----
    const float SCALE = 0.08838834764831845f;   // 1/sqrt(128)
    const float sc = (by == 0) ? SCALE : 1.0f;
#pragma unroll
    for (int i = 0; i < 2; i++) {
        int r0 = rg * 32 + i * 16 + g;
#pragma unroll
        for (int j = 0; j < 8; j++) {
            int c0 = cg * 64 + j * 8 + 2 * tig;
            float b0 = __ldg(bias + c0), b1 = __ldg(bias + c0 + 1);
            float4 a = acc[i][j];
            *(float2*)&sp[r0 * SP + c0]       = make_float2((a.x + b0) * sc, (a.y + b1) * sc);
            *(float2*)&sp[(r0 + 8) * SP + c0] = make_float2((a.z + b0) * sc, (a.w + b1) * sc);
        }
    }
    __syncthreads();

    const int bx = blockIdx.x;
    if (by == 0) {
        unsigned* dst = (unsigned*)(outg + (size_t)bx * 16384);
#pragma unroll
        for (int i = 0; i < 16; i++) {
            float v0 = sp[(w * 16 + g)     * SP + 8 * i + tig];
            float v1 = sp[(w * 16 + g + 8) * SP + 8 * i + tig];
            float v2 = sp[(w * 16 + g)     * SP + 8 * i + tig + 4];
            float v3 = sp[(w * 16 + g + 8) * SP + 8 * i + tig + 4];
            *(uint4*)(dst + ((w * 16 + i) * 32 + lane) * 4) =
                make_uint4(f2tf(v0), f2tf(v1), f2tf(v2), f2tf(v3));
        }
    } else if (by == 1) {
#pragma unroll
        for (int it = 0; it < 32; it++) {
            int idx = w * 32 + it;
            int kt = idx >> 7, j = (idx >> 4) & 7, s = idx & 15;
            int row = kt * 64 + 8 * j + g;
            float v0 = sp[row * SP + 8 * s + tig];
            float v1 = sp[row * SP + 8 * s + tig + 4];
            unsigned* dst = (unsigned*)(outg + (size_t)(2 * bx + kt) * 8192);
            *(uint2*)(dst + ((j * 16 + s) * 32 + lane) * 2) = make_uint2(f2tf(v0), f2tf(v1));
        }
    } else {
#pragma unroll
        for (int it = 0; it < 32; it++) {
            int idx = w * 32 + it;
            int kt = idx >> 7, ht = (idx >> 3) & 15, skv = idx & 7;
            float v0 = sp[(kt * 64 + 8 * skv + tig)     * SP + 8 * ht + g];
            float v1 = sp[(kt * 64 + 8 * skv + tig + 4) * SP + 8 * ht + g];
            unsigned* dst = (unsigned*)(outg + (size_t)(2 * bx + kt) * 8192);
            *(uint2*)(dst + ((ht * 8 + skv) * 32 + lane) * 2) = make_uint2(f2tf(v0), f2tf(v1));
        }
    }
}

// ---------------------------------------------------------------------------
// Kernel 2: flash attention. CTA = 64 q-rows, 128 threads (4 warps x 16 rows),
// Q A-frags in REGISTERS (LDG from packed g_q). kv tiles of 64, single smem
// buffer, K/V split cp.async groups (V latency hidden behind S+softmax).
// Grid: 32 x 8, each CTA handles paired q-tiles (bx, 63-bx) -> 65 kv-tiles each.
// smem: k 8192f | v 8192f | pf 4096f = 81920 B  -> 2 CTAs/SM.
// ---------------------------------------------------------------------------
#define ATT_SMEM (20480 * 4)

__global__ __launch_bounds__(128, 2) void attn_mma_kernel(float* __restrict__ out)
{
    extern __shared__ float sm[];
    unsigned* ksu = (unsigned*)sm;
    unsigned* vsu = (unsigned*)(sm + 8192);
    unsigned* pfu = (unsigned*)(sm + 16384);

    const int t    = threadIdx.x;
    const int w    = t >> 5;       // 0..3
    const int lane = t & 31;
    const int g    = lane >> 2;
    const int tig  = lane & 3;
    const int b    = blockIdx.y;
    const int bx   = blockIdx.x;   // 0..31

#pragma unroll 1
    for (int half = 0; half < 2; half++) {
        const int qtp = half ? (63 - bx) : bx;       // 64-row q-tile index

        // Q A-frags -> registers
        const unsigned* qg =
            (const unsigned*)(g_q + (size_t)(b * 32 + (qtp >> 1)) * 16384);
        const int rb = (qtp & 1) * 4 + w;
        uint4 Q[16];
#pragma unroll
        for (int s = 0; s < 16; s++)
            Q[s] = *(const uint4*)(qg + ((rb * 16 + s) * 32 + lane) * 4);

        float4 O[16];
#pragma unroll
        for (int ht = 0; ht < 16; ht++) O[ht] = make_float4(0.f, 0.f, 0.f, 0.f);
        float mrow[2] = {-3.0e38f, -3.0e38f};
        float lrow[2] = {0.f, 0.f};

        const int ntiles = qtp + 1;
        for (int st = 0; st < ntiles; st++) {
            const float* kg = g_k + (size_t)(b * 64 + st) * 8192;
            const float* vg = g_v + (size_t)(b * 64 + st) * 8192;
#pragma unroll
            for (int u = 0; u < 16; u++) {
                int idx = u * 128 + t;
                cpasync16(sm + idx * 4, kg + idx * 4);
            }
            CP_COMMIT();
#pragma unroll
            for (int u = 0; u < 16; u++) {
                int idx = u * 128 + t;
                cpasync16(sm + 8192 + idx * 4, vg + idx * 4);
            }
            CP_COMMIT();
            cp_wait<1>();          // K ready
            __syncthreads();

            // ---- S = Q @ K^T  (16 x 64 per warp) ----
            float4 sa[8];
#pragma unroll
            for (int j = 0; j < 8; j++) sa[j] = make_float4(0.f, 0.f, 0.f, 0.f);
#pragma unroll
            for (int s = 0; s < 16; s++) {
#pragma unroll
                for (int j = 0; j < 8; j++) {
                    uint2 bf = *(const uint2*)(ksu + ((j * 16 + s) * 32 + lane) * 2);
                    mma_tf32(sa[j], Q[s], bf);
                }
            }

            // ---- causal mask: only the diagonal tile ----
            if (st == qtp) {
                const int rbase = w * 16 + g;
#pragma unroll
                for (int j = 0; j < 8; j++) {
                    int kv0 = 8 * j + 2 * tig;
                    if (kv0     > rbase)     sa[j].x = -1.0e30f;
                    if (kv0 + 1 > rbase)     sa[j].y = -1.0e30f;
                    if (kv0     > rbase + 8) sa[j].z = -1.0e30f;
                    if (kv0 + 1 > rbase + 8) sa[j].w = -1.0e30f;
                }
            }

            // ---- online softmax (rows g, g+8; reduce over 4 tig lanes) ----
#pragma unroll
            for (int h = 0; h < 2; h++) {
                float lm = -3.0e38f;
#pragma unroll
                for (int j = 0; j < 8; j++) {
                    float v0 = h ? sa[j].z : sa[j].x;
                    float v1 = h ? sa[j].w : sa[j].y;
                    lm = fmaxf(lm, fmaxf(v0, v1));
                }
                lm = fmaxf(lm, __shfl_xor_sync(0xffffffffu, lm, 1));
                lm = fmaxf(lm, __shfl_xor_sync(0xffffffffu, lm, 2));
                float mn    = fmaxf(mrow[h], lm);
                float alpha = __expf(mrow[h] - mn);
                mrow[h] = mn;
                float ls = 0.f;
#pragma unroll
                for (int j = 0; j < 8; j++) {
                    float v0 = h ? sa[j].z : sa[j].x;
                    float v1 = h ? sa[j].w : sa[j].y;
                    v0 = __expf(v0 - mn);
                    v1 = __expf(v1 - mn);
                    if (h) { sa[j].z = v0; sa[j].w = v1; }
                    else   { sa[j].x = v0; sa[j].y = v1; }
                    ls += v0 + v1;
                }
                ls += __shfl_xor_sync(0xffffffffu, ls, 1);
                ls += __shfl_xor_sync(0xffffffffu, ls, 2);
                lrow[h] = lrow[h] * alpha + ls;
#pragma unroll
                for (int ht = 0; ht < 16; ht++) {
                    if (h) { O[ht].z *= alpha; O[ht].w *= alpha; }
                    else   { O[ht].x *= alpha; O[ht].y *= alpha; }
                }
            }

            // ---- P -> A-frags (warp-private smem bounce) ----
            {
                const int col0  = (2 * tig) & 3;
                const int tigHi = (tig >= 2) ? 2 : 0;
#pragma unroll
                for (int j = 0; j < 8; j++) {
                    int base = ((w * 8 + j) * 32 + g * 4 + col0) * 4 + tigHi;
                    pfu[base]     = f2tf(sa[j].x);
                    pfu[base + 4] = f2tf(sa[j].y);
                    pfu[base + 1] = f2tf(sa[j].z);
                    pfu[base + 5] = f2tf(sa[j].w);
                }
            }
            cp_wait<0>();          // V ready (this thread's group)
            __syncthreads();       // V + pf visible to all warps in CTA

            // ---- O += P @ V ----
#pragma unroll
            for (int skv = 0; skv < 8; skv++) {
                uint4 a = *(const uint4*)(pfu + ((w * 8 + skv) * 32 + lane) * 4);
#pragma unroll
                for (int ht = 0; ht < 16; ht++) {
                    uint2 bf = *(const uint2*)(vsu + ((ht * 8 + skv) * 32 + lane) * 2);
                    mma_tf32(O[ht], a, bf);
                }
            }
            __syncthreads();       // done with K/V/pf before next tile's loads
        }

        // ---- epilogue ----
        const float inv0 = 1.0f / lrow[0];
        const float inv1 = 1.0f / lrow[1];
        const int r0 = qtp * 64 + w * 16 + g;
        float* o0 = out + ((size_t)b * TT + r0) * HH;
        float* o1 = o0 + 8 * HH;
#pragma unroll
        for (int ht = 0; ht < 16; ht++) {
            int col = ht * 8 + 2 * tig;
            *(float2*)(o0 + col) = make_float2(O[ht].x * inv0, O[ht].y * inv0);
            *(float2*)(o1 + col) = make_float2(O[ht].z * inv1, O[ht].w * inv1);
        }
    }
}

// ---------------------------------------------------------------------------
extern "C" void kernel_launch(void* const* d_in, const int* in_sizes, int n_in,
                              void* d_out, int out_size)
{
    const float* x  = (const float*)d_in[0];
    const float* Wq = (const float*)d_in[1];
    const float* bq = (const float*)d_in[2];
    const float* Wk = (const float*)d_in[3];
    const float* bk = (const float*)d_in[4];
    const float* Wv = (const float*)d_in[5];
    const float* bv = (const float*)d_in[6];
    float* out = (float*)d_out;

    cudaFuncSetAttribute(qkv_mma_kernel,
                         cudaFuncAttributeMaxDynamicSharedMemorySize, QKV_SMEM);
    cudaFuncSetAttribute(attn_mma_kernel,
                         cudaFuncAttributeMaxDynamicSharedMemorySize, ATT_SMEM);

    qkv_mma_kernel<<<dim3(MM / 128, 3), 256, QKV_SMEM>>>(x, Wq, bq, Wk, bk, Wv, bv);
    attn_mma_kernel<<<dim3(32, BB), 128, ATT_SMEM>>>(out);
}

// round 4
// speedup vs baseline: 6.0286x; 1.0424x over previous
#include <cuda_runtime.h>
#include <cstdint>

#define BB 8
#define TT 4096
#define EE 1024
#define HH 128
#define MM (BB*TT)

// ---------------------------------------------------------------------------
// Scratch: q/k/v in tf32, PRE-PACKED into mma.sync fragment order.
// g_q: per 128-row tile: [rb*16+s][lane][4 words]  (A-frags)
// g_k: per 64-row kv tile: [j*16+s][lane][2 words] (B-frags for S=QK^T)
//      *** kv columns PERMUTED within each 8-col block: n = pi(kv) with
//          pi(c) = 2c (c<4), 2(c-4)+1 (c>=4)  -> S C-layout == PV A-frag order.
// g_v: per 64-row kv tile: [ht*8+skv][lane][2 words](B-frags for O=PV)
// ---------------------------------------------------------------------------
static __device__ __align__(16) float g_q[(size_t)MM * HH];
static __device__ __align__(16) float g_k[(size_t)MM * HH];
static __device__ __align__(16) float g_v[(size_t)MM * HH];

__device__ __forceinline__ unsigned f2tf(float f) {
    unsigned u;
    asm("cvt.rna.tf32.f32 %0, %1;" : "=r"(u) : "f"(f));
    return u;
}

__device__ __forceinline__ void mma_tf32(float4& d, const uint4& a, const uint2& b) {
    asm volatile(
        "mma.sync.aligned.m16n8k8.row.col.f32.tf32.tf32.f32 "
        "{%0,%1,%2,%3}, {%4,%5,%6,%7}, {%8,%9}, {%0,%1,%2,%3};"
        : "+f"(d.x), "+f"(d.y), "+f"(d.z), "+f"(d.w)
        : "r"(a.x), "r"(a.y), "r"(a.z), "r"(a.w), "r"(b.x), "r"(b.y));
}

__device__ __forceinline__ void cpasync16(void* sdst, const void* gsrc) {
    unsigned s = (unsigned)__cvta_generic_to_shared(sdst);
    asm volatile("cp.async.cg.shared.global [%0], [%1], 16;" :: "r"(s), "l"(gsrc));
}
#define CP_COMMIT() asm volatile("cp.async.commit_group;")
template <int N> __device__ __forceinline__ void cp_wait() {
    asm volatile("cp.async.wait_group %0;" :: "n"(N));
}

// ---------------------------------------------------------------------------
// Kernel 1: QKV GEMM (unchanged mainloop; K epilogue adds column permutation).
// ---------------------------------------------------------------------------
#define XST 36
#define WST 136
#define XBUF (128*XST)
#define WBUF (32*WST)
#define QKV_SMEM (17920*4)
#define SP 132

__global__ __launch_bounds__(256, 2) void qkv_mma_kernel(
    const float* __restrict__ x,
    const float* __restrict__ Wq, const float* __restrict__ bq,
    const float* __restrict__ Wk, const float* __restrict__ bk,
    const float* __restrict__ Wv, const float* __restrict__ bv)
{
    extern __shared__ float smq[];
    float* xsb[2] = { smq,           smq + XBUF };
    float* wsb[2] = { smq + 2*XBUF,  smq + 2*XBUF + WBUF };
    float* sp = smq;

    const int by = blockIdx.y;
    const float* W; const float* bias; float* outg;
    if (by == 0)      { W = Wq; bias = bq; outg = g_q; }
    else if (by == 1) { W = Wk; bias = bk; outg = g_k; }
    else              { W = Wv; bias = bv; outg = g_v; }

    const int t    = threadIdx.x;
    const int w    = t >> 5;
    const int lane = t & 31;
    const int g    = lane >> 2;
    const int tig  = lane & 3;
    const int rg   = w & 3;
    const int cg   = w >> 2;
    const int m0   = blockIdx.x * 128;

    float4 acc[2][8];
#pragma unroll
    for (int i = 0; i < 2; i++)
#pragma unroll
        for (int j = 0; j < 8; j++) acc[i][j] = make_float4(0.f, 0.f, 0.f, 0.f);

#define LOAD_CHUNK(KC, BUF) do {                                              \
        float* xd = xsb[BUF]; float* wd = wsb[BUF];                           \
        _Pragma("unroll")                                                     \
        for (int u = 0; u < 4; u++) {                                         \
            int idx = u * 256 + t;                                            \
            int row = idx >> 3, c4 = (idx & 7) * 4;                           \
            cpasync16(xd + row * XST + c4,                                    \
                      x + (size_t)(m0 + row) * EE + (KC) + c4);               \
        }                                                                     \
        _Pragma("unroll")                                                     \
        for (int u = 0; u < 4; u++) {                                         \
            int idx = u * 256 + t;                                            \
            int k = idx >> 5, c4 = (idx & 31) * 4;                            \
            cpasync16(wd + k * WST + c4,                                      \
                      W + (size_t)((KC) + k) * HH + c4);                      \
        }                                                                     \
        CP_COMMIT();                                                          \
    } while (0)

    LOAD_CHUNK(0, 0);

    for (int c = 0; c < 32; c++) {
        const int buf = c & 1;
        if (c < 31) { LOAD_CHUNK((c + 1) * 32, buf ^ 1); cp_wait<1>(); }
        else        { cp_wait<0>(); }
        __syncthreads();

        const float* xb = xsb[buf];
        const float* wb = wsb[buf];
#pragma unroll
        for (int s = 0; s < 4; s++) {
            uint4 a[2];
#pragma unroll
            for (int i = 0; i < 2; i++) {
                const float* xr0 = xb + ((2*rg + i)*16 + g)     * XST + s*8 + tig;
                const float* xr1 = xb + ((2*rg + i)*16 + g + 8) * XST + s*8 + tig;
                a[i].x = f2tf(xr0[0]); a[i].y = f2tf(xr1[0]);
                a[i].z = f2tf(xr0[4]); a[i].w = f2tf(xr1[4]);
            }
            const float* wr0 = wb + (s*8 + tig)     * WST + cg*64 + g;
            const float* wr1 = wb + (s*8 + tig + 4) * WST + cg*64 + g;
#pragma unroll
            for (int j = 0; j < 8; j++) {
                uint2 bf = make_uint2(f2tf(wr0[j*8]), f2tf(wr1[j*8]));
                mma_tf32(acc[0][j], a[0], bf);
                mma_tf32(acc[1][j], a[1], bf);
            }
        }
        __syncthreads();
    }

    // ---- epilogue: bias (+q scale) -> plain smem -> pack ----
    const float SCALE = 0.08838834764831845f;   // 1/sqrt(128)
    const float sc = (by == 0) ? SCALE : 1.0f;
#pragma unroll
    for (int i = 0; i < 2; i++) {
        int r0 = rg * 32 + i * 16 + g;
#pragma unroll
        for (int j = 0; j < 8; j++) {
            int c0 = cg * 64 + j * 8 + 2 * tig;
            float b0 = __ldg(bias + c0), b1 = __ldg(bias + c0 + 1);
            float4 a = acc[i][j];
            *(float2*)&sp[r0 * SP + c0]       = make_float2((a.x + b0) * sc, (a.y + b1) * sc);
            *(float2*)&sp[(r0 + 8) * SP + c0] = make_float2((a.z + b0) * sc, (a.w + b1) * sc);
        }
    }
    __syncthreads();

    const int bx = blockIdx.x;
    if (by == 0) {
        unsigned* dst = (unsigned*)(outg + (size_t)bx * 16384);
#pragma unroll
        for (int i = 0; i < 16; i++) {
            float v0 = sp[(w * 16 + g)     * SP + 8 * i + tig];
            float v1 = sp[(w * 16 + g + 8) * SP + 8 * i + tig];
            float v2 = sp[(w * 16 + g)     * SP + 8 * i + tig + 4];
            float v3 = sp[(w * 16 + g + 8) * SP + 8 * i + tig + 4];
            *(uint4*)(dst + ((w * 16 + i) * 32 + lane) * 4) =
                make_uint4(f2tf(v0), f2tf(v1), f2tf(v2), f2tf(v3));
        }
    } else if (by == 1) {
        // K pack with column permutation: n-position g holds kv row pi^-1(g)
        const int pg = (g >> 1) + ((g & 1) << 2);   // pi^-1(g)
#pragma unroll
        for (int it = 0; it < 32; it++) {
            int idx = w * 32 + it;
            int kt = idx >> 7, j = (idx >> 4) & 7, s = idx & 15;
            int row = kt * 64 + 8 * j + pg;
            float v0 = sp[row * SP + 8 * s + tig];
            float v1 = sp[row * SP + 8 * s + tig + 4];
            unsigned* dst = (unsigned*)(outg + (size_t)(2 * bx + kt) * 8192);
            *(uint2*)(dst + ((j * 16 + s) * 32 + lane) * 2) = make_uint2(f2tf(v0), f2tf(v1));
        }
    } else {
#pragma unroll
        for (int it = 0; it < 32; it++) {
            int idx = w * 32 + it;
            int kt = idx >> 7, ht = (idx >> 3) & 15, skv = idx & 7;
            float v0 = sp[(kt * 64 + 8 * skv + tig)     * SP + 8 * ht + g];
            float v1 = sp[(kt * 64 + 8 * skv + tig + 4) * SP + 8 * ht + g];
            unsigned* dst = (unsigned*)(outg + (size_t)(2 * bx + kt) * 8192);
            *(uint2*)(dst + ((ht * 8 + skv) * 32 + lane) * 2) = make_uint2(f2tf(v0), f2tf(v1));
        }
    }
}

// ---------------------------------------------------------------------------
// Kernel 2: flash attention. CTA = 64 q-rows, 128 threads. Q A-frags in regs.
// K double-buffered, V single-buffered (latency hidden by S+softmax / PV).
// P -> A-frags = pure register shuffle of components (K columns pre-permuted).
// smem: k[2] 8192f + v 8192f = 24576 f = 98304 B -> 2 CTAs/SM.
// Grid 32 x 8; CTA does q-tiles (bx, 63-bx): 65 kv-tiles each (balanced).
// ---------------------------------------------------------------------------
#define ATT_SMEM (24576 * 4)

__global__ __launch_bounds__(128, 2) void attn_mma_kernel(float* __restrict__ out)
{
    extern __shared__ float sm[];
    unsigned* kbu[2] = { (unsigned*)sm, (unsigned*)(sm + 8192) };
    unsigned* vsu = (unsigned*)(sm + 16384);

    const int t    = threadIdx.x;
    const int w    = t >> 5;
    const int lane = t & 31;
    const int g    = lane >> 2;
    const int tig  = lane & 3;
    const int b    = blockIdx.y;
    const int bx   = blockIdx.x;

#pragma unroll 1
    for (int half = 0; half < 2; half++) {
        const int qtp = half ? (63 - bx) : bx;

        // Q A-frags -> registers
        const unsigned* qg =
            (const unsigned*)(g_q + (size_t)(b * 32 + (qtp >> 1)) * 16384);
        const int rb = (qtp & 1) * 4 + w;
        uint4 Q[16];
#pragma unroll
        for (int s = 0; s < 16; s++)
            Q[s] = *(const uint4*)(qg + ((rb * 16 + s) * 32 + lane) * 4);

        float4 O[16];
#pragma unroll
        for (int ht = 0; ht < 16; ht++) O[ht] = make_float4(0.f, 0.f, 0.f, 0.f);
        float mrow[2] = {-3.0e38f, -3.0e38f};
        float lrow[2] = {0.f, 0.f};

        const int ntiles = qtp + 1;

        // prefetch K(0)
        {
            const float* kg = g_k + (size_t)(b * 64) * 8192;
#pragma unroll
            for (int u = 0; u < 16; u++) {
                int idx = u * 128 + t;
                cpasync16((float*)kbu[0] + idx * 4, kg + idx * 4);
            }
            CP_COMMIT();
        }

        for (int st = 0; st < ntiles; st++) {
            const int buf = st & 1;

            // issue V(st)  (V buffer free: prev PV finished before loop-end sync)
            {
                const float* vg = g_v + (size_t)(b * 64 + st) * 8192;
#pragma unroll
                for (int u = 0; u < 16; u++) {
                    int idx = u * 128 + t;
                    cpasync16((float*)vsu + idx * 4, vg + idx * 4);
                }
                CP_COMMIT();
            }
            cp_wait<1>();          // K(st) complete (V still in flight)
            __syncthreads();

            // ---- S = Q @ K^T  (16 x 64 per warp; columns pre-permuted) ----
            const unsigned* ksu = kbu[buf];
            float4 sa[8];
#pragma unroll
            for (int j = 0; j < 8; j++) sa[j] = make_float4(0.f, 0.f, 0.f, 0.f);
#pragma unroll
            for (int s = 0; s < 16; s++) {
#pragma unroll
                for (int j = 0; j < 8; j++) {
                    uint2 bf = *(const uint2*)(ksu + ((j * 16 + s) * 32 + lane) * 2);
                    mma_tf32(sa[j], Q[s], bf);
                }
            }

            // prefetch K(st+1) into the other buffer
            if (st + 1 < ntiles) {
                const float* kg = g_k + (size_t)(b * 64 + st + 1) * 8192;
#pragma unroll
                for (int u = 0; u < 16; u++) {
                    int idx = u * 128 + t;
                    cpasync16((float*)kbu[buf ^ 1] + idx * 4, kg + idx * 4);
                }
                CP_COMMIT();
            }

            // ---- causal mask (permuted mapping: .x <-> kv 8j+tig, .y <-> 8j+tig+4)
            if (st == qtp) {
                const int rbase = w * 16 + g;
#pragma unroll
                for (int j = 0; j < 8; j++) {
                    int kvx = 8 * j + tig;
                    if (kvx     > rbase)     sa[j].x = -1.0e30f;
                    if (kvx + 4 > rbase)     sa[j].y = -1.0e30f;
                    if (kvx     > rbase + 8) sa[j].z = -1.0e30f;
                    if (kvx + 4 > rbase + 8) sa[j].w = -1.0e30f;
                }
            }

            // ---- online softmax ----
#pragma unroll
            for (int h = 0; h < 2; h++) {
                float lm = -3.0e38f;
#pragma unroll
                for (int j = 0; j < 8; j++) {
                    float v0 = h ? sa[j].z : sa[j].x;
                    float v1 = h ? sa[j].w : sa[j].y;
                    lm = fmaxf(lm, fmaxf(v0, v1));
                }
                lm = fmaxf(lm, __shfl_xor_sync(0xffffffffu, lm, 1));
                lm = fmaxf(lm, __shfl_xor_sync(0xffffffffu, lm, 2));
                float mn    = fmaxf(mrow[h], lm);
                float alpha = __expf(mrow[h] - mn);
                mrow[h] = mn;
                float ls = 0.f;
#pragma unroll
                for (int j = 0; j < 8; j++) {
                    float v0 = h ? sa[j].z : sa[j].x;
                    float v1 = h ? sa[j].w : sa[j].y;
                    v0 = __expf(v0 - mn);
                    v1 = __expf(v1 - mn);
                    if (h) { sa[j].z = v0; sa[j].w = v1; }
                    else   { sa[j].x = v0; sa[j].y = v1; }
                    ls += v0 + v1;
                }
                ls += __shfl_xor_sync(0xffffffffu, ls, 1);
                ls += __shfl_xor_sync(0xffffffffu, ls, 2);
                lrow[h] = lrow[h] * alpha + ls;
#pragma unroll
                for (int ht = 0; ht < 16; ht++) {
                    if (h) { O[ht].z *= alpha; O[ht].w *= alpha; }
                    else   { O[ht].x *= alpha; O[ht].y *= alpha; }
                }
            }

            // ---- P A-frags: pure component reorder (no smem bounce) ----
            uint4 pa[8];
#pragma unroll
            for (int j = 0; j < 8; j++)
                pa[j] = make_uint4(f2tf(sa[j].x), f2tf(sa[j].z),
                                   f2tf(sa[j].y), f2tf(sa[j].w));

            if (st + 1 < ntiles) cp_wait<1>();   // V(st) done, K(st+1) flying
            else                 cp_wait<0>();
            __syncthreads();                     // V visible to all warps

            // ---- O += P @ V ----
#pragma unroll
            for (int skv = 0; skv < 8; skv++) {
#pragma unroll
                for (int ht = 0; ht < 16; ht++) {
                    uint2 bf = *(const uint2*)(vsu + ((ht * 8 + skv) * 32 + lane) * 2);
                    mma_tf32(O[ht], pa[skv], bf);
                }
            }
            __syncthreads();                     // protect V buffer for next issue
        }

        // ---- epilogue ----
        const float inv0 = 1.0f / lrow[0];
        const float inv1 = 1.0f / lrow[1];
        const int r0 = qtp * 64 + w * 16 + g;
        float* o0 = out + ((size_t)b * TT + r0) * HH;
        float* o1 = o0 + 8 * HH;
#pragma unroll
        for (int ht = 0; ht < 16; ht++) {
            int col = ht * 8 + 2 * tig;
            *(float2*)(o0 + col) = make_float2(O[ht].x * inv0, O[ht].y * inv0);
            *(float2*)(o1 + col) = make_float2(O[ht].z * inv1, O[ht].w * inv1);
        }
    }
}

// ---------------------------------------------------------------------------
extern "C" void kernel_launch(void* const* d_in, const int* in_sizes, int n_in,
                              void* d_out, int out_size)
{
    const float* x  = (const float*)d_in[0];
    const float* Wq = (const float*)d_in[1];
    const float* bq = (const float*)d_in[2];
    const float* Wk = (const float*)d_in[3];
    const float* bk = (const float*)d_in[4];
    const float* Wv = (const float*)d_in[5];
    const float* bv = (const float*)d_in[6];
    float* out = (float*)d_out;

    cudaFuncSetAttribute(qkv_mma_kernel,
                         cudaFuncAttributeMaxDynamicSharedMemorySize, QKV_SMEM);
    cudaFuncSetAttribute(attn_mma_kernel,
                         cudaFuncAttributeMaxDynamicSharedMemorySize, ATT_SMEM);

    qkv_mma_kernel<<<dim3(MM / 128, 3), 256, QKV_SMEM>>>(x, Wq, bq, Wk, bk, Wv, bv);
    attn_mma_kernel<<<dim3(32, BB), 128, ATT_SMEM>>>(out);
}

// round 5
// speedup vs baseline: 6.4859x; 1.0759x over previous
#include <cuda_runtime.h>
#include <cstdint>

#define BB 8
#define TT 4096
#define EE 1024
#define HH 128
#define MM (BB*TT)

// ---------------------------------------------------------------------------
// Scratch (tf32, pre-packed into mma.sync fragment order):
// g_q: per 128-row tile: [rb*16+s][lane][4 words]  (A-frags)
// g_k: per 64-row kv tile: [j*16+s][lane][2 words] (B-frags, kv cols permuted
//      pi(c)=2c / 2(c-4)+1 so the S C-layout equals the PV A-frag order)
// g_v: per 64-row kv tile: [ht*8+skv][lane][2 words]
// g_wp: W pre-packed B-frags: [by][kc 0..31][J 0..15][s 0..3][lane][2 words]
// ---------------------------------------------------------------------------
static __device__ __align__(16) float g_q[(size_t)MM * HH];
static __device__ __align__(16) float g_k[(size_t)MM * HH];
static __device__ __align__(16) float g_v[(size_t)MM * HH];
static __device__ __align__(16) float g_wp[3u * EE * HH];

__device__ __forceinline__ unsigned f2tf(float f) {
    unsigned u;
    asm("cvt.rna.tf32.f32 %0, %1;" : "=r"(u) : "f"(f));
    return u;
}

__device__ __forceinline__ void mma_tf32(float4& d, const uint4& a, const uint2& b) {
    asm volatile(
        "mma.sync.aligned.m16n8k8.row.col.f32.tf32.tf32.f32 "
        "{%0,%1,%2,%3}, {%4,%5,%6,%7}, {%8,%9}, {%0,%1,%2,%3};"
        : "+f"(d.x), "+f"(d.y), "+f"(d.z), "+f"(d.w)
        : "r"(a.x), "r"(a.y), "r"(a.z), "r"(a.w), "r"(b.x), "r"(b.y));
}

__device__ __forceinline__ void cpasync16(void* sdst, const void* gsrc) {
    unsigned s = (unsigned)__cvta_generic_to_shared(sdst);
    asm volatile("cp.async.cg.shared.global [%0], [%1], 16;" :: "r"(s), "l"(gsrc));
}
#define CP_COMMIT() asm volatile("cp.async.commit_group;")
template <int N> __device__ __forceinline__ void cp_wait() {
    asm volatile("cp.async.wait_group %0;" :: "n"(N));
}

// ---------------------------------------------------------------------------
// Kernel 0: one-shot W pre-pack into B-frag tf32 layout (runs in ~µs).
// word0 = W[kc*32 + s*8 + tig][J*8 + g], word1 = same with k+4.
// ---------------------------------------------------------------------------
__global__ __launch_bounds__(256) void wpack_kernel(
    const float* __restrict__ Wq, const float* __restrict__ Wk,
    const float* __restrict__ Wv)
{
    const int kc = blockIdx.x;
    const int by = blockIdx.y;
    const float* W = (by == 0) ? Wq : (by == 1) ? Wk : Wv;
    unsigned* dst = (unsigned*)(g_wp + (size_t)by * (EE * HH) + kc * 4096);
    const int t = threadIdx.x;
#pragma unroll
    for (int u = 0; u < 8; u++) {
        int idx = u * 256 + t;              // (J,s,lane)
        int J = idx >> 7, s = (idx >> 5) & 3, lane = idx & 31;
        int g = lane >> 2, tig = lane & 3;
        int k0 = kc * 32 + s * 8 + tig;
        int n  = J * 8 + g;
        dst[idx * 2]     = f2tf(W[(size_t)k0 * HH + n]);
        dst[idx * 2 + 1] = f2tf(W[(size_t)(k0 + 4) * HH + n]);
    }
}

// ---------------------------------------------------------------------------
// Kernel 1: QKV GEMM. CTA 128x128, K-chunks of 32 double-buffered. x via
// padded smem + gather/cvt; W via pre-packed frags (LDS.64, no cvt).
// smem: xs[2] 128x36f + wf[2] 4096f = 17408 f; epilogue sp 128x132 = 16896 f.
// ---------------------------------------------------------------------------
#define XST 36
#define XBUF (128*XST)     // 4608
#define WBUF 4096
#define QKV_SMEM (17408*4)
#define SP 132

__global__ __launch_bounds__(256, 2) void qkv_mma_kernel(
    const float* __restrict__ x,
    const float* __restrict__ bq, const float* __restrict__ bk,
    const float* __restrict__ bv)
{
    extern __shared__ float smq[];
    float* xsb[2] = { smq,           smq + XBUF };
    float* wsb[2] = { smq + 2*XBUF,  smq + 2*XBUF + WBUF };
    float* sp = smq;

    const int by = blockIdx.y;
    const float* bias = (by == 0) ? bq : (by == 1) ? bk : bv;
    float* outg = (by == 0) ? g_q : (by == 1) ? g_k : g_v;
    const float* wp = g_wp + (size_t)by * (EE * HH);

    const int t    = threadIdx.x;
    const int w    = t >> 5;
    const int lane = t & 31;
    const int g    = lane >> 2;
    const int tig  = lane & 3;
    const int rg   = w & 3;
    const int cg   = w >> 2;
    const int m0   = blockIdx.x * 128;

    float4 acc[2][8];
#pragma unroll
    for (int i = 0; i < 2; i++)
#pragma unroll
        for (int j = 0; j < 8; j++) acc[i][j] = make_float4(0.f, 0.f, 0.f, 0.f);

#define LOAD_CHUNK(KC, BUF) do {                                              \
        float* xd = xsb[BUF]; float* wd = wsb[BUF];                           \
        _Pragma("unroll")                                                     \
        for (int u = 0; u < 4; u++) {                                         \
            int idx = u * 256 + t;                                            \
            int row = idx >> 3, c4 = (idx & 7) * 4;                           \
            cpasync16(xd + row * XST + c4,                                    \
                      x + (size_t)(m0 + row) * EE + (KC) + c4);               \
        }                                                                     \
        _Pragma("unroll")                                                     \
        for (int u = 0; u < 4; u++) {                                         \
            int idx = u * 256 + t;                                            \
            cpasync16(wd + idx * 4, wp + ((KC) >> 5) * 4096 + idx * 4);       \
        }                                                                     \
        CP_COMMIT();                                                          \
    } while (0)

    LOAD_CHUNK(0, 0);

    for (int c = 0; c < 32; c++) {
        const int buf = c & 1;
        if (c < 31) { LOAD_CHUNK((c + 1) * 32, buf ^ 1); cp_wait<1>(); }
        else        { cp_wait<0>(); }
        __syncthreads();

        const float* xb = xsb[buf];
        const uint2* wb2 = (const uint2*)wsb[buf];
#pragma unroll
        for (int s = 0; s < 4; s++) {
            uint4 a[2];
#pragma unroll
            for (int i = 0; i < 2; i++) {
                const float* xr0 = xb + ((2*rg + i)*16 + g)     * XST + s*8 + tig;
                const float* xr1 = xb + ((2*rg + i)*16 + g + 8) * XST + s*8 + tig;
                a[i].x = f2tf(xr0[0]); a[i].y = f2tf(xr1[0]);
                a[i].z = f2tf(xr0[4]); a[i].w = f2tf(xr1[4]);
            }
#pragma unroll
            for (int j = 0; j < 8; j++) {
                uint2 bf = wb2[(((cg * 8 + j) * 4 + s) * 32) + lane];
                mma_tf32(acc[0][j], a[0], bf);
                mma_tf32(acc[1][j], a[1], bf);
            }
        }
        __syncthreads();
    }

    // ---- epilogue: bias (+q scale) -> plain smem -> pack ----
    const float SCALE = 0.08838834764831845f;
    const float sc = (by == 0) ? SCALE : 1.0f;
#pragma unroll
    for (int i = 0; i < 2; i++) {
        int r0 = rg * 32 + i * 16 + g;
#pragma unroll
        for (int j = 0; j < 8; j++) {
            int c0 = cg * 64 + j * 8 + 2 * tig;
            float b0 = __ldg(bias + c0), b1 = __ldg(bias + c0 + 1);
            float4 a = acc[i][j];
            *(float2*)&sp[r0 * SP + c0]       = make_float2((a.x + b0) * sc, (a.y + b1) * sc);
            *(float2*)&sp[(r0 + 8) * SP + c0] = make_float2((a.z + b0) * sc, (a.w + b1) * sc);
        }
    }
    __syncthreads();

    const int bx = blockIdx.x;
    if (by == 0) {
        unsigned* dst = (unsigned*)(outg + (size_t)bx * 16384);
#pragma unroll
        for (int i = 0; i < 16; i++) {
            float v0 = sp[(w * 16 + g)     * SP + 8 * i + tig];
            float v1 = sp[(w * 16 + g + 8) * SP + 8 * i + tig];
            float v2 = sp[(w * 16 + g)     * SP + 8 * i + tig + 4];
            float v3 = sp[(w * 16 + g + 8) * SP + 8 * i + tig + 4];
            *(uint4*)(dst + ((w * 16 + i) * 32 + lane) * 4) =
                make_uint4(f2tf(v0), f2tf(v1), f2tf(v2), f2tf(v3));
        }
    } else if (by == 1) {
        const int pg = (g >> 1) + ((g & 1) << 2);   // pi^-1(g)
#pragma unroll
        for (int it = 0; it < 32; it++) {
            int idx = w * 32 + it;
            int kt = idx >> 7, j = (idx >> 4) & 7, s = idx & 15;
            int row = kt * 64 + 8 * j + pg;
            float v0 = sp[row * SP + 8 * s + tig];
            float v1 = sp[row * SP + 8 * s + tig + 4];
            unsigned* dst = (unsigned*)(outg + (size_t)(2 * bx + kt) * 8192);
            *(uint2*)(dst + ((j * 16 + s) * 32 + lane) * 2) = make_uint2(f2tf(v0), f2tf(v1));
        }
    } else {
#pragma unroll
        for (int it = 0; it < 32; it++) {
            int idx = w * 32 + it;
            int kt = idx >> 7, ht = (idx >> 3) & 15, skv = idx & 7;
            float v0 = sp[(kt * 64 + 8 * skv + tig)     * SP + 8 * ht + g];
            float v1 = sp[(kt * 64 + 8 * skv + tig + 4) * SP + 8 * ht + g];
            unsigned* dst = (unsigned*)(outg + (size_t)(2 * bx + kt) * 8192);
            *(uint2*)(dst + ((ht * 8 + skv) * 32 + lane) * 2) = make_uint2(f2tf(v0), f2tf(v1));
        }
    }
}

// ---------------------------------------------------------------------------
// Kernel 2: flash attention, deferred-PV pipeline.
// CTA = 128 q-rows, 256 threads (8 warps x 16 rows). Q A-frags in regs.
// K and V both double-buffered (smem 128KB, 1 CTA/SM).
// Iter st: wait K(st)+V(st-1) -> issue V(st),K(st+1) -> S(st) mma ->
//          O*=alpha, PV(st-1) mma -> softmax(st) (overlaps PV drain).
// Grid 16 x 8; CTA does 128-row q-tiles (bx, 31-bx): 66 kv-iters (balanced).
// ---------------------------------------------------------------------------
#define ATT_SMEM (32768 * 4)   // 131072 B

__global__ __launch_bounds__(256, 1) void attn_mma_kernel(float* __restrict__ out)
{
    extern __shared__ float sm[];
    unsigned* kbu[2] = { (unsigned*)sm,             (unsigned*)(sm + 8192) };
    unsigned* vbu[2] = { (unsigned*)(sm + 16384),   (unsigned*)(sm + 24576) };

    const int t    = threadIdx.x;
    const int w    = t >> 5;       // 0..7
    const int lane = t & 31;
    const int g    = lane >> 2;
    const int tig  = lane & 3;
    const int b    = blockIdx.y;
    const int bx   = blockIdx.x;   // 0..15

#pragma unroll 1
    for (int half = 0; half < 2; half++) {
        const int qt = half ? (31 - bx) : bx;   // 128-row q-tile

        // Q A-frags -> registers (rb = w)
        const unsigned* qg = (const unsigned*)(g_q + (size_t)(b * 32 + qt) * 16384);
        uint4 Q[16];
#pragma unroll
        for (int s = 0; s < 16; s++)
            Q[s] = *(const uint4*)(qg + ((w * 16 + s) * 32 + lane) * 4);

        float4 O[16];
#pragma unroll
        for (int ht = 0; ht < 16; ht++) O[ht] = make_float4(0.f, 0.f, 0.f, 0.f);
        float mrow[2] = {-3.0e38f, -3.0e38f};
        float lrow[2] = {0.f, 0.f};
        float aprev[2] = {1.f, 1.f};
        uint4 pa[8];

        const int ntiles = 2 * qt + 2;

        // prologue: K(0)
        {
            const float* kg = g_k + (size_t)(b * 64) * 8192;
#pragma unroll
            for (int u = 0; u < 8; u++) {
                int idx = u * 256 + t;
                cpasync16((float*)kbu[0] + idx * 4, kg + idx * 4);
            }
            CP_COMMIT();
        }

#pragma unroll 1
        for (int st = 0; st < ntiles; st++) {
            const int p = st & 1;

            cp_wait<0>();          // K(st) + V(st-1) complete
            __syncthreads();

            // issue V(st), K(st+1) — they fly during S + PV + softmax
            {
                const float* vg = g_v + (size_t)(b * 64 + st) * 8192;
#pragma unroll
                for (int u = 0; u < 8; u++) {
                    int idx = u * 256 + t;
                    cpasync16((float*)vbu[p] + idx * 4, vg + idx * 4);
                }
                CP_COMMIT();
            }
            if (st + 1 < ntiles) {
                const float* kg = g_k + (size_t)(b * 64 + st + 1) * 8192;
#pragma unroll
                for (int u = 0; u < 8; u++) {
                    int idx = u * 256 + t;
                    cpasync16((float*)kbu[p ^ 1] + idx * 4, kg + idx * 4);
                }
                CP_COMMIT();
            }

            // ---- S = Q @ K^T  (16 x 64 per warp) ----
            const unsigned* ksu = kbu[p];
            float4 sa[8];
#pragma unroll
            for (int j = 0; j < 8; j++) sa[j] = make_float4(0.f, 0.f, 0.f, 0.f);
#pragma unroll
            for (int s = 0; s < 16; s++) {
#pragma unroll
                for (int j = 0; j < 8; j++) {
                    uint2 bf = *(const uint2*)(ksu + ((j * 16 + s) * 32 + lane) * 2);
                    mma_tf32(sa[j], Q[s], bf);
                }
            }

            // ---- deferred: O *= alpha(st-1); O += P(st-1) @ V(st-1) ----
            if (st > 0) {
#pragma unroll
                for (int ht = 0; ht < 16; ht++) {
                    O[ht].x *= aprev[0]; O[ht].y *= aprev[0];
                    O[ht].z *= aprev[1]; O[ht].w *= aprev[1];
                }
                const unsigned* vsu = vbu[p ^ 1];
#pragma unroll
                for (int skv = 0; skv < 8; skv++) {
#pragma unroll
                    for (int ht = 0; ht < 16; ht++) {
                        uint2 bf = *(const uint2*)(vsu + ((ht * 8 + skv) * 32 + lane) * 2);
                        mma_tf32(O[ht], pa[skv], bf);
                    }
                }
            }

            // ---- causal mask (x<->kv 8j+tig, y<->8j+tig+4, permuted K) ----
            if (st >= 2 * qt) {
                const int rbase = qt * 128 + w * 16 + g;
#pragma unroll
                for (int j = 0; j < 8; j++) {
                    int kvx = st * 64 + 8 * j + tig;
                    if (kvx     > rbase)     sa[j].x = -1.0e30f;
                    if (kvx + 4 > rbase)     sa[j].y = -1.0e30f;
                    if (kvx     > rbase + 8) sa[j].z = -1.0e30f;
                    if (kvx + 4 > rbase + 8) sa[j].w = -1.0e30f;
                }
            }

            // ---- softmax(st): stats + exp + pack pa (no O touch) ----
#pragma unroll
            for (int h = 0; h < 2; h++) {
                float lm = -3.0e38f;
#pragma unroll
                for (int j = 0; j < 8; j++) {
                    float v0 = h ? sa[j].z : sa[j].x;
                    float v1 = h ? sa[j].w : sa[j].y;
                    lm = fmaxf(lm, fmaxf(v0, v1));
                }
                lm = fmaxf(lm, __shfl_xor_sync(0xffffffffu, lm, 1));
                lm = fmaxf(lm, __shfl_xor_sync(0xffffffffu, lm, 2));
                float mn = fmaxf(mrow[h], lm);
                aprev[h] = __expf(mrow[h] - mn);
                mrow[h] = mn;
                float ls = 0.f;
#pragma unroll
                for (int j = 0; j < 8; j++) {
                    float v0 = h ? sa[j].z : sa[j].x;
                    float v1 = h ? sa[j].w : sa[j].y;
                    v0 = __expf(v0 - mn);
                    v1 = __expf(v1 - mn);
                    if (h) { sa[j].z = v0; sa[j].w = v1; }
                    else   { sa[j].x = v0; sa[j].y = v1; }
                    ls += v0 + v1;
                }
                ls += __shfl_xor_sync(0xffffffffu, ls, 1);
                ls += __shfl_xor_sync(0xffffffffu, ls, 2);
                lrow[h] = lrow[h] * aprev[h] + ls;
            }
#pragma unroll
            for (int j = 0; j < 8; j++)
                pa[j] = make_uint4(f2tf(sa[j].x), f2tf(sa[j].z),
                                   f2tf(sa[j].y), f2tf(sa[j].w));
        }

        // ---- epilogue: final deferred PV, then normalize + store ----
        cp_wait<0>();
        __syncthreads();
        {
#pragma unroll
            for (int ht = 0; ht < 16; ht++) {
                O[ht].x *= aprev[0]; O[ht].y *= aprev[0];
                O[ht].z *= aprev[1]; O[ht].w *= aprev[1];
            }
            const unsigned* vsu = vbu[(ntiles - 1) & 1];
#pragma unroll
            for (int skv = 0; skv < 8; skv++) {
#pragma unroll
                for (int ht = 0; ht < 16; ht++) {
                    uint2 bf = *(const uint2*)(vsu + ((ht * 8 + skv) * 32 + lane) * 2);
                    mma_tf32(O[ht], pa[skv], bf);
                }
            }
        }
        __syncthreads();   // buffers reusable next half

        const float inv0 = 1.0f / lrow[0];
        const float inv1 = 1.0f / lrow[1];
        const int r0 = qt * 128 + w * 16 + g;
        float* o0 = out + ((size_t)b * TT + r0) * HH;
        float* o1 = o0 + 8 * HH;
#pragma unroll
        for (int ht = 0; ht < 16; ht++) {
            int col = ht * 8 + 2 * tig;
            *(float2*)(o0 + col) = make_float2(O[ht].x * inv0, O[ht].y * inv0);
            *(float2*)(o1 + col) = make_float2(O[ht].z * inv1, O[ht].w * inv1);
        }
    }
}

// ---------------------------------------------------------------------------
extern "C" void kernel_launch(void* const* d_in, const int* in_sizes, int n_in,
                              void* d_out, int out_size)
{
    const float* x  = (const float*)d_in[0];
    const float* Wq = (const float*)d_in[1];
    const float* bq = (const float*)d_in[2];
    const float* Wk = (const float*)d_in[3];
    const float* bk = (const float*)d_in[4];
    const float* Wv = (const float*)d_in[5];
    const float* bv = (const float*)d_in[6];
    float* out = (float*)d_out;

    cudaFuncSetAttribute(qkv_mma_kernel,
                         cudaFuncAttributeMaxDynamicSharedMemorySize, QKV_SMEM);
    cudaFuncSetAttribute(attn_mma_kernel,
                         cudaFuncAttributeMaxDynamicSharedMemorySize, ATT_SMEM);

    wpack_kernel<<<dim3(32, 3), 256>>>(Wq, Wk, Wv);
    qkv_mma_kernel<<<dim3(MM / 128, 3), 256, QKV_SMEM>>>(x, bq, bk, bv);
    attn_mma_kernel<<<dim3(16, BB), 256, ATT_SMEM>>>(out);
}